// round 5
// baseline (speedup 1.0000x reference)
#include <cuda_runtime.h>

// ============================================================================
// AdaMLP: gathered-expert 2-layer MLP (1024 slots, 64 experts, 256->1024->256).
// R4: depth-2 register pipeline on weight LDGs (kill exposed DRAM latency),
//     z-split chunk parallelism, smem-atomic grouping, wider reduce grid,
//     probe kernel to rotate ncu capture onto a GEMM.
// ============================================================================

typedef unsigned long long u64;

#define NEXP 64
#define NSLOT 1024
#define DIM 256
#define RDIM 1024
#define SC 16          // slots per chunk
#define SPAD 20        // smem row stride in floats (16 + 4)

__device__ int   g_cnt[NEXP];
__device__ int   g_list[NEXP * NSLOT];
__device__ int   g_slot_e[NSLOT];
__device__ float g_H[NSLOT * RDIM];          // 4 MB hidden (post-ReLU)
__device__ float g_P[4 * NSLOT * DIM];       // 4 MB partial outputs (4 r-segments)
__device__ int   g_probe[32];

__device__ __forceinline__ u64 pack2(float x, float y) {
    u64 r;
    asm("mov.b64 %0, {%1,%2};" : "=l"(r) : "f"(x), "f"(y));
    return r;
}
__device__ __forceinline__ void fma2(u64& d, u64 a, u64 b) {
    asm("fma.rn.f32x2 %0, %1, %2, %0;" : "+l"(d) : "l"(a), "l"(b));
}
__device__ __forceinline__ float2 unpack2(u64 v) {
    float lo, hi;
    asm("mov.b64 {%0,%1}, %2;" : "=f"(lo), "=f"(hi) : "l"(v));
    return make_float2(lo, hi);
}

// ----------------------------------------------------------------------------
// Group slots by expert (smem atomics). List order is atomic-order dependent,
// but every slot's math is independent of its list position -> output is
// bitwise deterministic regardless.
// ----------------------------------------------------------------------------
__global__ void group_kernel(const int* __restrict__ idx32) {
    int tid = threadIdx.x;
    __shared__ int s_cnt[NEXP];
    __shared__ int s_flag;
    if (tid == 0) s_flag = 0;
    if (tid < NEXP) s_cnt[tid] = 0;
    __syncthreads();
    if (tid < 512) {
        if (idx32[2 * tid + 1] != 0) atomicOr(&s_flag, 1);
    }
    __syncthreads();
    int e = s_flag ? idx32[tid] : idx32[2 * tid];   // int32 vs int64 auto-detect
    e &= (NEXP - 1);
    g_slot_e[tid] = e;
    int p = atomicAdd(&s_cnt[e], 1);
    g_list[e * NSLOT + p] = tid;
    __syncthreads();
    if (tid < NEXP) g_cnt[tid] = s_cnt[tid];
}

// ----------------------------------------------------------------------------
// GEMM1: H[s, r] = relu( sum_d slots[s,d] * w1[e,d,r] + b1[e,r] )
// grid (8 r-tiles of 128, 64 experts, 2 chunk-groups), 128 threads, 1 col/thr.
// Depth-2 register pipeline on the 8-wide weight loads.
// ----------------------------------------------------------------------------
__global__ __launch_bounds__(128) void gemm1_kernel(
    const float* __restrict__ slots,
    const float* __restrict__ w1,
    const float* __restrict__ b1)
{
    int e = blockIdx.y;
    int n = g_cnt[e];
    int z = blockIdx.z;
    if (z * SC >= n) return;
    int c = blockIdx.x * 128 + threadIdx.x;
    int tid = threadIdx.x;

    __shared__ __align__(16) float ssl[DIM * SPAD];
    __shared__ int sid[SC];

    const float* Wp = w1 + (size_t)e * (DIM * RDIM) + c;
    float b = b1[(size_t)e * RDIM + c];

    for (int s0 = z * SC; s0 < n; s0 += 2 * SC) {
        int sc = min(SC, n - s0);
        if (tid < SC) sid[tid] = (tid < sc) ? g_list[e * NSLOT + s0 + tid] : 0;
        __syncthreads();
#pragma unroll
        for (int j = 0; j < SC; j++) {
            int valid = j < sc;
            int sj = sid[j];
#pragma unroll
            for (int dd = 0; dd < 2; dd++) {
                int d = tid + dd * 128;
                float v = 0.0f;
                if (valid) v = slots[(size_t)sj * DIM + d];
                ssl[d * SPAD + j] = v;
            }
        }
        __syncthreads();

        u64 acc[8];
#pragma unroll
        for (int p = 0; p < 8; p++) acc[p] = 0ull;

        float wreg[2][8];
#pragma unroll
        for (int i = 0; i < 8; i++) wreg[0][i] = Wp[(size_t)i * RDIM];

        for (int dd = 0; dd < DIM; dd += 8) {
            int cur = (dd >> 3) & 1, nxt = cur ^ 1;
            if (dd + 8 < DIM) {
#pragma unroll
                for (int i = 0; i < 8; i++)
                    wreg[nxt][i] = Wp[(size_t)(dd + 8 + i) * RDIM];
            }
#pragma unroll
            for (int i = 0; i < 8; i++) {
                u64 ww = pack2(wreg[cur][i], wreg[cur][i]);
                const ulonglong2* sp = (const ulonglong2*)(ssl + (dd + i) * SPAD);
#pragma unroll
                for (int q = 0; q < 4; q++) {
                    ulonglong2 s = sp[q];
                    fma2(acc[2 * q], s.x, ww);
                    fma2(acc[2 * q + 1], s.y, ww);
                }
            }
        }

#pragma unroll
        for (int q = 0; q < 4; q++) {
            float2 a0 = unpack2(acc[2 * q]);
            float2 a1 = unpack2(acc[2 * q + 1]);
            int j = 4 * q;
            if (j + 0 < sc) g_H[(size_t)sid[j + 0] * RDIM + c] = fmaxf(a0.x + b, 0.0f);
            if (j + 1 < sc) g_H[(size_t)sid[j + 1] * RDIM + c] = fmaxf(a0.y + b, 0.0f);
            if (j + 2 < sc) g_H[(size_t)sid[j + 2] * RDIM + c] = fmaxf(a1.x + b, 0.0f);
            if (j + 3 < sc) g_H[(size_t)sid[j + 3] * RDIM + c] = fmaxf(a1.y + b, 0.0f);
        }
        __syncthreads();
    }
}

// ----------------------------------------------------------------------------
// GEMM2 (partial): P[seg, s, dc] = sum_{r in seg} H[s, r] * w2[e, r, dc]
// grid (4 segs * 2 dc-tiles, 64 experts, 2 chunk-groups), 128 thr, 1 col/thr.
// ----------------------------------------------------------------------------
__global__ __launch_bounds__(128) void gemm2_kernel(const float* __restrict__ w2)
{
    int e = blockIdx.y;
    int n = g_cnt[e];
    int z = blockIdx.z;
    if (z * SC >= n) return;
    int seg   = blockIdx.x >> 1;
    int rbase = seg * 256;
    int c     = (blockIdx.x & 1) * 128 + threadIdx.x;
    int tid = threadIdx.x;

    __shared__ __align__(16) float hs[256 * SPAD];
    __shared__ int sid[SC];

    const float* Wp = w2 + (size_t)e * (RDIM * DIM) + (size_t)rbase * DIM + c;
    float* Pp = g_P + (size_t)seg * (NSLOT * DIM);

    for (int s0 = z * SC; s0 < n; s0 += 2 * SC) {
        int sc = min(SC, n - s0);
        if (tid < SC) sid[tid] = (tid < sc) ? g_list[e * NSLOT + s0 + tid] : 0;
        __syncthreads();
#pragma unroll
        for (int j = 0; j < SC; j++) {
            int valid = j < sc;
            int sj = sid[j];
#pragma unroll
            for (int rr = 0; rr < 2; rr++) {
                int r = tid + rr * 128;
                float v = 0.0f;
                if (valid) v = g_H[(size_t)sj * RDIM + rbase + r];
                hs[r * SPAD + j] = v;
            }
        }
        __syncthreads();

        u64 acc[8];
#pragma unroll
        for (int p = 0; p < 8; p++) acc[p] = 0ull;

        float wreg[2][8];
#pragma unroll
        for (int i = 0; i < 8; i++) wreg[0][i] = Wp[(size_t)i * DIM];

        for (int rr = 0; rr < 256; rr += 8) {
            int cur = (rr >> 3) & 1, nxt = cur ^ 1;
            if (rr + 8 < 256) {
#pragma unroll
                for (int i = 0; i < 8; i++)
                    wreg[nxt][i] = Wp[(size_t)(rr + 8 + i) * DIM];
            }
#pragma unroll
            for (int i = 0; i < 8; i++) {
                u64 ww = pack2(wreg[cur][i], wreg[cur][i]);
                const ulonglong2* sp = (const ulonglong2*)(hs + (rr + i) * SPAD);
#pragma unroll
                for (int q = 0; q < 4; q++) {
                    ulonglong2 s = sp[q];
                    fma2(acc[2 * q], s.x, ww);
                    fma2(acc[2 * q + 1], s.y, ww);
                }
            }
        }

#pragma unroll
        for (int q = 0; q < 4; q++) {
            float2 a0 = unpack2(acc[2 * q]);
            float2 a1 = unpack2(acc[2 * q + 1]);
            int j = 4 * q;
            if (j + 0 < sc) Pp[(size_t)sid[j + 0] * DIM + c] = a0.x;
            if (j + 1 < sc) Pp[(size_t)sid[j + 1] * DIM + c] = a0.y;
            if (j + 2 < sc) Pp[(size_t)sid[j + 2] * DIM + c] = a1.x;
            if (j + 3 < sc) Pp[(size_t)sid[j + 3] * DIM + c] = a1.y;
        }
        __syncthreads();
    }
}

// ----------------------------------------------------------------------------
// Reduce: out[s, :] = sum_seg P[seg, s, :] + b2[e(s), :]
// ----------------------------------------------------------------------------
__global__ __launch_bounds__(128) void reduce_kernel(
    const float* __restrict__ b2, float* __restrict__ out)
{
    int t = blockIdx.x * 128 + threadIdx.x;   // float4 index, 65536 total
    int slot = t >> 6;
    int e = g_slot_e[slot];
    const float4* P = (const float4*)g_P;
    const int SEG = NSLOT * DIM / 4;
    float4 v0 = P[t];
    float4 v1 = P[SEG + t];
    float4 v2 = P[2 * SEG + t];
    float4 v3 = P[3 * SEG + t];
    float4 bb = ((const float4*)b2)[e * 64 + (t & 63)];
    float4 r;
    r.x = v0.x + v1.x + v2.x + v3.x + bb.x;
    r.y = v0.y + v1.y + v2.y + v3.y + bb.y;
    r.z = v0.z + v1.z + v2.z + v3.z + bb.z;
    r.w = v0.w + v1.w + v2.w + v3.w + bb.w;
    ((float4*)out)[t] = r;
}

// Rotates the launch period from 4 to 5 so ncu's fixed capture slot lands on
// a GEMM instead of reduce_kernel. Deterministic, allocation-free.
__global__ void probe_kernel() { g_probe[threadIdx.x] = threadIdx.x; }

// ----------------------------------------------------------------------------
extern "C" void kernel_launch(void* const* d_in, const int* in_sizes, int n_in,
                              void* d_out, int out_size)
{
    const float* slots = (const float*)d_in[0];
    const float* w1    = (const float*)d_in[1];
    const float* b1    = (const float*)d_in[2];
    const float* w2    = (const float*)d_in[3];
    const float* b2    = (const float*)d_in[4];
    const int*   idx   = (const int*)d_in[5];
    float* out = (float*)d_out;

    group_kernel<<<1, 1024>>>(idx);
    gemm1_kernel<<<dim3(8, NEXP, 2), 128>>>(slots, w1, b1);
    gemm2_kernel<<<dim3(8, NEXP, 2), 128>>>(w2);
    reduce_kernel<<<512, 128>>>(b2, out);
    probe_kernel<<<1, 32>>>();
}

// round 8
// speedup vs baseline: 2.3191x; 2.3191x over previous
#include <cuda_runtime.h>

// ============================================================================
// AdaMLP fused persistent kernel (R5).
// 1024 slots, 64 experts, 256 -> 1024(relu) -> 256, fp32 exact (FFMA2 path).
// One launch: phase0 per-CTA grouping (smem) | phase1 GEMM1 -> g_H |
// grid barrier | phase2 GEMM2 (4 r-segments) -> g_P | grid barrier |
// phase3 reduce + b2 -> out.
// grid 512 x 128thr, launch_bounds(128,4): all CTAs resident (148 SMs, occ 4).
// ============================================================================

typedef unsigned long long u64;

#define NEXP 64
#define NSLOT 1024
#define DIM 256
#define RDIM 1024
#define SC 16
#define SPAD 20
#define GRID 512

__device__ float g_H[NSLOT * RDIM];          // 4 MB hidden (post-ReLU)
__device__ float g_P[4 * NSLOT * DIM];       // 4 MB partials (4 r-segments)
__device__ unsigned g_bar_cnt = 0;
__device__ unsigned g_bar_gen = 0;           // monotonically grows across replays

__device__ __forceinline__ u64 pack2(float x, float y) {
    u64 r; asm("mov.b64 %0, {%1,%2};" : "=l"(r) : "f"(x), "f"(y)); return r;
}
__device__ __forceinline__ void fma2(u64& d, u64 a, u64 b) {
    asm("fma.rn.f32x2 %0, %1, %2, %0;" : "+l"(d) : "l"(a), "l"(b));
}
__device__ __forceinline__ float2 unpack2(u64 v) {
    float lo, hi; asm("mov.b64 {%0,%1}, %2;" : "=f"(lo), "=f"(hi) : "l"(v));
    return make_float2(lo, hi);
}

// Grid-wide barrier: counting + generation, gpu-scope fences. Self-resetting
// (cnt returns to 0; gen monotone, compared against captured value).
__device__ __forceinline__ void grid_barrier() {
    __syncthreads();
    if (threadIdx.x == 0) {
        __threadfence();
        volatile unsigned* genp = &g_bar_gen;
        unsigned g = *genp;
        if (atomicAdd(&g_bar_cnt, 1u) == gridDim.x - 1) {
            g_bar_cnt = 0;
            __threadfence();
            atomicAdd(&g_bar_gen, 1u);
        } else {
            while (*genp == g) { __nanosleep(64); }
        }
        __threadfence();
    }
    __syncthreads();
}

__global__ __launch_bounds__(128, 4) void fused_kernel(
    const float* __restrict__ slots,
    const float* __restrict__ w1,
    const float* __restrict__ b1,
    const float* __restrict__ w2,
    const float* __restrict__ b2,
    const int*   __restrict__ idx,
    float* __restrict__ out)
{
    __shared__ int s_cnt[NEXP];
    __shared__ int s_base[NEXP];
    __shared__ int s_cur[NEXP];
    __shared__ int s_list[NSLOT];
    __shared__ __align__(16) float sbuf[DIM * SPAD];   // 20 KB
    __shared__ int s_flag;

    const int tid = threadIdx.x;
    const int bid = blockIdx.x;

    // ---------------- phase 0: per-CTA grouping (smem only) -----------------
    if (tid < NEXP) s_cnt[tid] = 0;
    if (tid == 0) s_flag = 0;
    __syncthreads();
    // int64-vs-int32 detect: int64 values in [0,64) have zero odd 32-bit words
    for (int t = tid; t < 512; t += 128)
        if (idx[2 * t + 1] != 0) s_flag = 1;    // benign race, all write 1
    __syncthreads();
    const int flag = s_flag;
    for (int s = tid; s < NSLOT; s += 128) {
        int e = (flag ? idx[s] : idx[2 * s]) & (NEXP - 1);
        atomicAdd(&s_cnt[e], 1);
    }
    __syncthreads();
    if (tid == 0) {
        int run = 0;
        for (int e = 0; e < NEXP; e++) { s_base[e] = run; run += s_cnt[e]; }
    }
    __syncthreads();
    if (tid < NEXP) s_cur[tid] = s_base[tid];
    __syncthreads();
    for (int s = tid; s < NSLOT; s += 128) {
        int e = (flag ? idx[s] : idx[2 * s]) & (NEXP - 1);
        s_list[atomicAdd(&s_cur[e], 1)] = s;   // order nondet; per-slot math
    }                                          // is position-independent
    __syncthreads();

    // ---------------- phase 1: GEMM1 (H = relu(slots @ w1 + b1)) ------------
    {
        const int e = bid >> 3, rtile = bid & 7;
        const int n = s_cnt[e], base = s_base[e];
        const int c = rtile * 128 + tid;
        const float* Wp = w1 + (size_t)e * (DIM * RDIM) + c;
        const float bias = b1[(size_t)e * RDIM + c];

        for (int s0 = 0; s0 < n; s0 += SC) {
            const int sc = min(SC, n - s0);
            // two-pass register-batched fill: 32 LDGs in flight
            float va[SC], vb[SC];
#pragma unroll
            for (int j = 0; j < SC; j++) {
                va[j] = 0.0f; vb[j] = 0.0f;
                if (j < sc) {
                    int sj = s_list[base + s0 + j];
                    va[j] = slots[(size_t)sj * DIM + tid];
                    vb[j] = slots[(size_t)sj * DIM + 128 + tid];
                }
            }
            __syncthreads();                    // prev-chunk readers done
#pragma unroll
            for (int j = 0; j < SC; j++) {
                sbuf[tid * SPAD + j] = va[j];
                sbuf[(128 + tid) * SPAD + j] = vb[j];
            }
            __syncthreads();

            u64 acc[8];
#pragma unroll
            for (int p = 0; p < 8; p++) acc[p] = 0ull;

            for (int dd = 0; dd < DIM; dd += 16) {
                float w[16];
#pragma unroll
                for (int i = 0; i < 16; i++) w[i] = Wp[(size_t)(dd + i) * RDIM];
#pragma unroll
                for (int i = 0; i < 16; i++) {
                    u64 ww = pack2(w[i], w[i]);
                    const ulonglong2* sp = (const ulonglong2*)(sbuf + (dd + i) * SPAD);
#pragma unroll
                    for (int q = 0; q < 4; q++) {
                        ulonglong2 sv = sp[q];
                        fma2(acc[2 * q], sv.x, ww);
                        fma2(acc[2 * q + 1], sv.y, ww);
                    }
                }
            }
#pragma unroll
            for (int q = 0; q < 4; q++) {
                float2 a0 = unpack2(acc[2 * q]);
                float2 a1 = unpack2(acc[2 * q + 1]);
                int j = 4 * q;
                if (j + 0 < sc) g_H[(size_t)s_list[base + s0 + j + 0] * RDIM + c] = fmaxf(a0.x + bias, 0.0f);
                if (j + 1 < sc) g_H[(size_t)s_list[base + s0 + j + 1] * RDIM + c] = fmaxf(a0.y + bias, 0.0f);
                if (j + 2 < sc) g_H[(size_t)s_list[base + s0 + j + 2] * RDIM + c] = fmaxf(a1.x + bias, 0.0f);
                if (j + 3 < sc) g_H[(size_t)s_list[base + s0 + j + 3] * RDIM + c] = fmaxf(a1.y + bias, 0.0f);
            }
        }
    }

    grid_barrier();

    // ---------------- phase 2: GEMM2 partials (P[seg] = H_seg @ w2_seg) -----
    {
        const int e = bid >> 3, sub = bid & 7;
        const int seg = sub >> 1, rbase = seg * 256;
        const int c = (sub & 1) * 128 + tid;
        const int n = s_cnt[e], base = s_base[e];
        const float* Wp = w2 + (size_t)e * (RDIM * DIM) + (size_t)rbase * DIM + c;
        float* Pp = g_P + (size_t)seg * (NSLOT * DIM);

        for (int s0 = 0; s0 < n; s0 += SC) {
            const int sc = min(SC, n - s0);
            float va[SC], vb[SC];
#pragma unroll
            for (int j = 0; j < SC; j++) {
                va[j] = 0.0f; vb[j] = 0.0f;
                if (j < sc) {
                    int sj = s_list[base + s0 + j];
                    va[j] = g_H[(size_t)sj * RDIM + rbase + tid];
                    vb[j] = g_H[(size_t)sj * RDIM + rbase + 128 + tid];
                }
            }
            __syncthreads();
#pragma unroll
            for (int j = 0; j < SC; j++) {
                sbuf[tid * SPAD + j] = va[j];
                sbuf[(128 + tid) * SPAD + j] = vb[j];
            }
            __syncthreads();

            u64 acc[8];
#pragma unroll
            for (int p = 0; p < 8; p++) acc[p] = 0ull;

            for (int rr = 0; rr < 256; rr += 16) {
                float w[16];
#pragma unroll
                for (int i = 0; i < 16; i++) w[i] = Wp[(size_t)(rr + i) * DIM];
#pragma unroll
                for (int i = 0; i < 16; i++) {
                    u64 ww = pack2(w[i], w[i]);
                    const ulonglong2* sp = (const ulonglong2*)(sbuf + (rr + i) * SPAD);
#pragma unroll
                    for (int q = 0; q < 4; q++) {
                        ulonglong2 sv = sp[q];
                        fma2(acc[2 * q], sv.x, ww);
                        fma2(acc[2 * q + 1], sv.y, ww);
                    }
                }
            }
#pragma unroll
            for (int q = 0; q < 4; q++) {
                float2 a0 = unpack2(acc[2 * q]);
                float2 a1 = unpack2(acc[2 * q + 1]);
                int j = 4 * q;
                if (j + 0 < sc) Pp[(size_t)s_list[base + s0 + j + 0] * DIM + c] = a0.x;
                if (j + 1 < sc) Pp[(size_t)s_list[base + s0 + j + 1] * DIM + c] = a0.y;
                if (j + 2 < sc) Pp[(size_t)s_list[base + s0 + j + 2] * DIM + c] = a1.x;
                if (j + 3 < sc) Pp[(size_t)s_list[base + s0 + j + 3] * DIM + c] = a1.y;
            }
        }
    }

    grid_barrier();

    // ---------------- phase 3: reduce partials + b2 -> out -------------------
    {
        int t = bid * 128 + tid;                 // float4 index; 512*128 = 65536
        int slot = t >> 6;
        int e = (flag ? idx[slot] : idx[2 * slot]) & (NEXP - 1);
        const float4* P4 = (const float4*)g_P;
        const int SEG = NSLOT * DIM / 4;
        float4 v0 = P4[t];
        float4 v1 = P4[SEG + t];
        float4 v2 = P4[2 * SEG + t];
        float4 v3 = P4[3 * SEG + t];
        float4 bb = ((const float4*)b2)[e * 64 + (t & 63)];
        float4 r;
        r.x = v0.x + v1.x + v2.x + v3.x + bb.x;
        r.y = v0.y + v1.y + v2.y + v3.y + bb.y;
        r.z = v0.z + v1.z + v2.z + v3.z + bb.z;
        r.w = v0.w + v1.w + v2.w + v3.w + bb.w;
        ((float4*)out)[t] = r;
    }
}

// ----------------------------------------------------------------------------
extern "C" void kernel_launch(void* const* d_in, const int* in_sizes, int n_in,
                              void* d_out, int out_size)
{
    const float* slots = (const float*)d_in[0];
    const float* w1    = (const float*)d_in[1];
    const float* b1    = (const float*)d_in[2];
    const float* w2    = (const float*)d_in[3];
    const float* b2    = (const float*)d_in[4];
    const int*   idx   = (const int*)d_in[5];
    float* out = (float*)d_out;

    fused_kernel<<<GRID, 128>>>(slots, w1, b1, w2, b2, idx, out);
}